// round 16
// baseline (speedup 1.0000x reference)
#include <cuda_runtime.h>
#include <cuda_bf16.h>
#include <cuda_fp16.h>
#include <cstdint>
#include <cstddef>

#define B_SZ   32
#define LP     2048
#define LQ     512
#define DMODEL 256

#define N_X (B_SZ*LP*DMODEL)
#define N_Y (B_SZ*LQ*DMODEL)
#define N_W (DMODEL*DMODEL)
#define N_S ((size_t)B_SZ*LP*LQ)

__device__ __align__(1024) unsigned char g_scratch[
    2ull*N_X + 2ull*N_Y +               // x16, y16 fp16
    4ull*N_W +                           // W fp16 hi/lo
    2ull*N_Y +                           // yT fp16
    2ull*N_X +                           // xp fp16 single
    4ull*N_Y +                           // yp fp16 hi/lo
    4ull*N_S +                           // S fp32
    2ull*N_S                             // P fp16
];

// ---------------- helpers ----------------
__device__ __forceinline__ uint32_t s_u32(const void* p) {
    return (uint32_t)__cvta_generic_to_shared(p);
}
__device__ __forceinline__ void ldsm4(uint32_t* r, uint32_t a) {
    asm volatile("ldmatrix.sync.aligned.m8n8.x4.shared.b16 {%0,%1,%2,%3}, [%4];"
                 : "=r"(r[0]), "=r"(r[1]), "=r"(r[2]), "=r"(r[3]) : "r"(a));
}
__device__ __forceinline__ void mma_f16(float* c, const uint32_t* a, const uint32_t* b) {
    asm volatile("mma.sync.aligned.m16n8k16.row.col.f32.f16.f16.f32 "
                 "{%0,%1,%2,%3}, {%4,%5,%6,%7}, {%8,%9}, {%0,%1,%2,%3};"
                 : "+f"(c[0]), "+f"(c[1]), "+f"(c[2]), "+f"(c[3])
                 : "r"(a[0]), "r"(a[1]), "r"(a[2]), "r"(a[3]), "r"(b[0]), "r"(b[1]));
}
#define CPA16(s, g) asm volatile("cp.async.cg.shared.global [%0], [%1], 16;" :: "r"(s), "l"(g))

// ---------------- prep kernels ----------------
__global__ void cvt_half_kernel(const float4* __restrict__ src,
                                uint4* __restrict__ dst, int n8) {
    int i = blockIdx.x * blockDim.x + threadIdx.x;
    int st = gridDim.x * blockDim.x;
    for (; i < n8; i += st) {
        float4 a = src[2 * i], b = src[2 * i + 1];
        __half2 h0 = __floats2half2_rn(a.x, a.y);
        __half2 h1 = __floats2half2_rn(a.z, a.w);
        __half2 h2 = __floats2half2_rn(b.x, b.y);
        __half2 h3 = __floats2half2_rn(b.z, b.w);
        dst[i] = make_uint4(*reinterpret_cast<uint32_t*>(&h0),
                            *reinterpret_cast<uint32_t*>(&h1),
                            *reinterpret_cast<uint32_t*>(&h2),
                            *reinterpret_cast<uint32_t*>(&h3));
    }
}

__global__ void split16_kernel(const float4* __restrict__ src,
                               uint4* __restrict__ hi,
                               uint4* __restrict__ lo, int n8) {
    int i = blockIdx.x * blockDim.x + threadIdx.x;
    int st = gridDim.x * blockDim.x;
    for (; i < n8; i += st) {
        float4 a = src[2 * i], b = src[2 * i + 1];
        float v[8] = {a.x, a.y, a.z, a.w, b.x, b.y, b.z, b.w};
        uint32_t H[4], L[4];
#pragma unroll
        for (int j = 0; j < 4; ++j) {
            __half h0 = __float2half_rn(v[2*j]);
            __half h1 = __float2half_rn(v[2*j+1]);
            __half2 hh = __halves2half2(h0, h1);
            __half2 ll = __floats2half2_rn(v[2*j]   - __half2float(h0),
                                           v[2*j+1] - __half2float(h1));
            H[j] = *reinterpret_cast<uint32_t*>(&hh);
            L[j] = *reinterpret_cast<uint32_t*>(&ll);
        }
        hi[i] = make_uint4(H[0], H[1], H[2], H[3]);
        lo[i] = make_uint4(L[0], L[1], L[2], L[3]);
    }
}

// y [B,LQ,D] -> y16 fp16 AND yT fp16 [B,D,LQ], one read of y
__global__ void y_prep_kernel(const float* __restrict__ y,
                              __half* __restrict__ y16,
                              __half* __restrict__ t) {
    __shared__ float tile[32][33];
    int b = blockIdx.z, q0 = blockIdx.y * 32, d0 = blockIdx.x * 32;
    int tx = threadIdx.x & 31, ty = threadIdx.x >> 5;
    const float* yb = y + ((size_t)b * LQ + q0) * DMODEL + d0;
    __half* y16b = y16 + ((size_t)b * LQ + q0) * DMODEL + d0;
#pragma unroll
    for (int j = 0; j < 32; j += 8) {
        float v = yb[(size_t)(ty + j) * DMODEL + tx];
        tile[ty + j][tx] = v;
        y16b[(size_t)(ty + j) * DMODEL + tx] = __float2half_rn(v);
    }
    __syncthreads();
    __half* tb = t + ((size_t)b * DMODEL + d0) * LQ + q0;
#pragma unroll
    for (int j = 0; j < 32; j += 8)
        tb[(size_t)(ty + j) * LQ + tx] = __float2half_rn(tile[tx][ty + j]);
}

// ---------------------------------------------------------------------------
// Tiling: 128x128 CTA tile, 8 warps (2x4), warp tile 64x32, KC=32.
// Proj/scores: 3-stage cp.async, rolled loop (regs<=124 -> 2 CTAs/SM).
// ---------------------------------------------------------------------------
#define TM  128
#define TN  128
#define KC  32
#define SLD 40
#define TSZ (TM*SLD)

// ---------------------------------------------------------------------------
// Proj: 2-MMA fp16 GEMM, 3-stage. A = x16/y16 merged, B = W fp16 hi/lo.
// ---------------------------------------------------------------------------
template<int KT>
__global__ void __launch_bounds__(256) gemm_proj_kernel(
    const __half* __restrict__ A1, const __half* __restrict__ A2,
    const __half* __restrict__ Wh, const __half* __restrict__ Wl,
    __half* __restrict__ Xp,
    __half* __restrict__ YpH, __half* __restrict__ YpL,
    const float* __restrict__ bias, int N, int Msplit)
{
    extern __shared__ __align__(16) __half dynp[];
    __half* sA_ = dynp;                 // 3 stages x TSZ
    __half* sBh = dynp + 3 * TSZ;
    __half* sBl = dynp + 6 * TSZ;

    const int tid = threadIdx.x;
    int m0 = blockIdx.y * TM;
    const int n0 = blockIdx.x * TN;

    const __half* Au = A1;
    const bool isY = (int)blockIdx.y >= Msplit;
    if (isY) { Au = A2; m0 = ((int)blockIdx.y - Msplit) * TM; }

    const int r0l = tid >> 2, hl = (tid & 3) * 8;
    const __half* pA  = Au + (size_t)m0 * KT;
    const __half* pBh = Wh + (size_t)n0 * KT;
    const __half* pBl = Wl + (size_t)n0 * KT;

#define LOAD_CHUNK(c, buf) do {                                               \
        const int _ko = (c) * KC;                                             \
        _Pragma("unroll")                                                     \
        for (int _i = 0; _i < 2; ++_i) {                                      \
            int _r = _i * 64 + r0l;                                           \
            int _so = (buf) * TSZ + _r * SLD + hl;                            \
            size_t _go = (size_t)_r * KT + _ko + hl;                          \
            CPA16(s_u32(sA_ + _so), pA  + _go);                               \
            CPA16(s_u32(sBh + _so), pBh + _go);                               \
            CPA16(s_u32(sBl + _so), pBl + _go);                               \
        }                                                                     \
        asm volatile("cp.async.commit_group;" ::: "memory");                  \
    } while (0)

    const int lane = tid & 31, warp = tid >> 5;
    const int wr = warp >> 2, wc = warp & 3;
    const int g = lane >> 2, t4 = lane & 3;
    const int aRow = wr * 64 + (lane & 15);
    const int aColH = (lane >> 4) << 3;
    const int bRow = wc * 32 + ((lane >> 4) << 3) + (lane & 7);
    const int bColH = ((lane >> 3) & 1) << 3;

    float acc[4][4][4];
#pragma unroll
    for (int m = 0; m < 4; ++m)
#pragma unroll
        for (int n = 0; n < 4; ++n)
#pragma unroll
            for (int k = 0; k < 4; ++k) acc[m][n][k] = 0.0f;

    constexpr int NC = KT / KC;     // 8
    LOAD_CHUNK(0, 0);
    LOAD_CHUNK(1, 1);
#pragma unroll 1
    for (int c = 0; c < NC; ++c) {
        if (c < NC - 1) asm volatile("cp.async.wait_group 1;" ::: "memory");
        else            asm volatile("cp.async.wait_group 0;" ::: "memory");
        __syncthreads();
        if (c + 2 < NC) LOAD_CHUNK(c + 2, (c + 2) % 3);
        const int off = (c % 3) * TSZ;

#pragma unroll
        for (int ks = 0; ks < 2; ++ks) {
            const int kc = ks * 16;
            uint32_t ah[4][4], bh[4][2], bl[4][2];
#pragma unroll
            for (int m = 0; m < 4; ++m)
                ldsm4(ah[m], s_u32(sA_ + off + (aRow + m * 16) * SLD + kc + aColH));
#pragma unroll
            for (int nb = 0; nb < 2; ++nb) {
                int bo = off + (bRow + nb * 16) * SLD + kc + bColH;
                uint32_t qh[4], ql[4];
                ldsm4(qh, s_u32(sBh + bo));
                ldsm4(ql, s_u32(sBl + bo));
                bh[2*nb][0] = qh[0]; bh[2*nb][1] = qh[1];
                bh[2*nb+1][0] = qh[2]; bh[2*nb+1][1] = qh[3];
                bl[2*nb][0] = ql[0]; bl[2*nb][1] = ql[1];
                bl[2*nb+1][0] = ql[2]; bl[2*nb+1][1] = ql[3];
            }
#pragma unroll
            for (int m = 0; m < 4; ++m)
#pragma unroll
                for (int n = 0; n < 4; ++n) {
                    mma_f16(acc[m][n], ah[m], bh[n]);
                    mma_f16(acc[m][n], ah[m], bl[n]);
                }
        }
    }
#undef LOAD_CHUNK

#pragma unroll
    for (int m = 0; m < 4; ++m) {
#pragma unroll
        for (int n = 0; n < 4; ++n) {
            int r0 = m0 + wr * 64 + m * 16 + g;
            int c0 = n0 + wc * 32 + n * 8 + 2 * t4;
            size_t o0 = (size_t)r0 * N + c0;
            size_t o1 = o0 + (size_t)8 * N;
            float b0 = __ldg(bias + c0), b1 = __ldg(bias + c0 + 1);
            float a0 = fmaxf(acc[m][n][0] + b0, 0.0f);
            float a1 = fmaxf(acc[m][n][1] + b1, 0.0f);
            float a2 = fmaxf(acc[m][n][2] + b0, 0.0f);
            float a3 = fmaxf(acc[m][n][3] + b1, 0.0f);
            if (!isY) {
                *reinterpret_cast<__half2*>(Xp + o0) = __floats2half2_rn(a0, a1);
                *reinterpret_cast<__half2*>(Xp + o1) = __floats2half2_rn(a2, a3);
            } else {
                __half h0 = __float2half_rn(a0), h1 = __float2half_rn(a1);
                __half h2 = __float2half_rn(a2), h3 = __float2half_rn(a3);
                *reinterpret_cast<__half2*>(YpH + o0) = __halves2half2(h0, h1);
                *reinterpret_cast<__half2*>(YpH + o1) = __halves2half2(h2, h3);
                *reinterpret_cast<__half2*>(YpL + o0) = __floats2half2_rn(
                    a0 - __half2float(h0), a1 - __half2float(h1));
                *reinterpret_cast<__half2*>(YpL + o1) = __floats2half2_rn(
                    a2 - __half2float(h2), a3 - __half2float(h3));
            }
        }
    }
}

// ---------------------------------------------------------------------------
// Scores: S[b] = Xp[b] @ (YpH[b]+YpL[b])^T — fp16, 2 MMAs, 3-stage, rolled.
// ---------------------------------------------------------------------------
template<int KT>
__global__ void __launch_bounds__(256) gemm_scores_kernel(
    const __half* __restrict__ A,
    const __half* __restrict__ BH, const __half* __restrict__ BL,
    float* __restrict__ Cf, int N,
    long long sA, long long sB, long long sC)
{
    extern __shared__ __align__(16) __half dynh[];
    __half* sA_ = dynh;
    __half* sBh = dynh + 3 * TSZ;
    __half* sBl = dynh + 6 * TSZ;

    const int tid = threadIdx.x;
    const int bz = blockIdx.z;
    const int m0 = blockIdx.y * TM, n0 = blockIdx.x * TN;

    const int r0l = tid >> 2, hl = (tid & 3) * 8;
    const __half* pA  = A  + bz * sA + (size_t)m0 * KT;
    const __half* pBh = BH + bz * sB + (size_t)n0 * KT;
    const __half* pBl = BL + bz * sB + (size_t)n0 * KT;

#define LOAD_SC(c, buf) do {                                                  \
        const int _ko = (c) * KC;                                             \
        _Pragma("unroll")                                                     \
        for (int _i = 0; _i < 2; ++_i) {                                      \
            int _r = _i * 64 + r0l;                                           \
            int _so = (buf) * TSZ + _r * SLD + hl;                            \
            size_t _go = (size_t)_r * KT + _ko + hl;                          \
            CPA16(s_u32(sA_ + _so), pA  + _go);                               \
            CPA16(s_u32(sBh + _so), pBh + _go);                               \
            CPA16(s_u32(sBl + _so), pBl + _go);                               \
        }                                                                     \
        asm volatile("cp.async.commit_group;" ::: "memory");                  \
    } while (0)

    const int lane = tid & 31, warp = tid >> 5;
    const int wr = warp >> 2, wc = warp & 3;
    const int g = lane >> 2, t4 = lane & 3;
    const int aRow = wr * 64 + (lane & 15);
    const int aColH = (lane >> 4) << 3;
    const int bRow = wc * 32 + ((lane >> 4) << 3) + (lane & 7);
    const int bColH = ((lane >> 3) & 1) << 3;

    float acc[4][4][4];
#pragma unroll
    for (int m = 0; m < 4; ++m)
#pragma unroll
        for (int n = 0; n < 4; ++n)
#pragma unroll
            for (int k = 0; k < 4; ++k) acc[m][n][k] = 0.0f;

    constexpr int NC = KT / KC;     // 8
    LOAD_SC(0, 0);
    LOAD_SC(1, 1);
#pragma unroll 1
    for (int c = 0; c < NC; ++c) {
        if (c < NC - 1) asm volatile("cp.async.wait_group 1;" ::: "memory");
        else            asm volatile("cp.async.wait_group 0;" ::: "memory");
        __syncthreads();
        if (c + 2 < NC) LOAD_SC(c + 2, (c + 2) % 3);
        const int off = (c % 3) * TSZ;

#pragma unroll
        for (int ks = 0; ks < 2; ++ks) {
            const int kc = ks * 16;
            uint32_t ah[4][4], bh[4][2], bl[4][2];
#pragma unroll
            for (int m = 0; m < 4; ++m)
                ldsm4(ah[m], s_u32(sA_ + off + (aRow + m * 16) * SLD + kc + aColH));
#pragma unroll
            for (int nb = 0; nb < 2; ++nb) {
                int bo = off + (bRow + nb * 16) * SLD + kc + bColH;
                uint32_t qh[4], ql[4];
                ldsm4(qh, s_u32(sBh + bo));
                ldsm4(ql, s_u32(sBl + bo));
                bh[2*nb][0] = qh[0]; bh[2*nb][1] = qh[1];
                bh[2*nb+1][0] = qh[2]; bh[2*nb+1][1] = qh[3];
                bl[2*nb][0] = ql[0]; bl[2*nb][1] = ql[1];
                bl[2*nb+1][0] = ql[2]; bl[2*nb+1][1] = ql[3];
            }
#pragma unroll
            for (int m = 0; m < 4; ++m)
#pragma unroll
                for (int n = 0; n < 4; ++n) {
                    mma_f16(acc[m][n], ah[m], bh[n]);
                    mma_f16(acc[m][n], ah[m], bl[n]);
                }
        }
    }
#undef LOAD_SC

    const size_t cBase = (size_t)((long long)bz * sC);
#pragma unroll
    for (int m = 0; m < 4; ++m) {
#pragma unroll
        for (int n = 0; n < 4; ++n) {
            int r0 = m0 + wr * 64 + m * 16 + g;
            int c0 = n0 + wc * 32 + n * 8 + 2 * t4;
            size_t o0 = cBase + (size_t)r0 * N + c0;
            size_t o1 = o0 + (size_t)8 * N;
            *reinterpret_cast<float2*>(Cf + o0) = make_float2(acc[m][n][0], acc[m][n][1]);
            *reinterpret_cast<float2*>(Cf + o1) = make_float2(acc[m][n][2], acc[m][n][3]);
        }
    }
}

// ---------------------------------------------------------------------------
// AV: fp16 GEMM, CTA tile 128x256, 512 threads, 3-stage, unrolled (R15-proven).
// ---------------------------------------------------------------------------
#define AV_BSZ (256*SLD)

template<int KT>
__global__ void __launch_bounds__(512) gemm_av_kernel(
    const __half* __restrict__ A, const __half* __restrict__ B,
    float* __restrict__ Cf,
    long long sA, long long sB, long long sC)
{
    extern __shared__ __align__(16) __half dynav[];
    __half* sA_ = dynav;                 // 3 x TSZ
    __half* sB_ = dynav + 3 * TSZ;       // 3 x AV_BSZ

    const int tid = threadIdx.x;
    const int bz = blockIdx.z;
    const int m0 = blockIdx.y * TM;

    const __half* pA = A + bz * sA + (size_t)m0 * KT;
    const __half* pB = B + bz * sB;

    const int rA = tid >> 2, hA = (tid & 3) * 8;

#define LOAD_AV(c, buf) do {                                                  \
        const int _ko = (c) * KC;                                             \
        CPA16(s_u32(sA_ + (buf) * TSZ + rA * SLD + hA),                       \
              pA + (size_t)rA * KT + _ko + hA);                               \
        _Pragma("unroll")                                                     \
        for (int _i = 0; _i < 2; ++_i) {                                      \
            int _idx = _i * 512 + tid;                                        \
            int _r = _idx >> 2, _h = (_idx & 3) * 8;                          \
            CPA16(s_u32(sB_ + (buf) * AV_BSZ + _r * SLD + _h),                \
                  pB + (size_t)_r * KT + _ko + _h);                           \
        }                                                                     \
        asm volatile("cp.async.commit_group;" ::: "memory");                  \
    } while (0)

    const int lane = tid & 31, warp = tid >> 5;
    const int wr = warp >> 3, wc = warp & 7;
    const int g = lane >> 2, t4 = lane & 3;
    const int aRow = wr * 64 + (lane & 15);
    const int aColH = (lane >> 4) << 3;
    const int bRow = wc * 32 + ((lane >> 4) << 3) + (lane & 7);
    const int bColH = ((lane >> 3) & 1) << 3;

    float acc[4][4][4];
#pragma unroll
    for (int m = 0; m < 4; ++m)
#pragma unroll
        for (int n = 0; n < 4; ++n)
#pragma unroll
            for (int k = 0; k < 4; ++k) acc[m][n][k] = 0.0f;

    constexpr int NC = KT / KC;     // 16
    LOAD_AV(0, 0);
    LOAD_AV(1, 1);
#pragma unroll 1
    for (int c = 0; c < NC; ++c) {
        if (c < NC - 1) asm volatile("cp.async.wait_group 1;" ::: "memory");
        else            asm volatile("cp.async.wait_group 0;" ::: "memory");
        __syncthreads();
        if (c + 2 < NC) LOAD_AV(c + 2, (c + 2) % 3);
        const int offA = (c % 3) * TSZ, offB = (c % 3) * AV_BSZ;

#pragma unroll
        for (int ks = 0; ks < 2; ++ks) {
            const int kc = ks * 16;
            uint32_t ah[4][4], bh[4][2];
#pragma unroll
            for (int m = 0; m < 4; ++m)
                ldsm4(ah[m], s_u32(sA_ + offA + (aRow + m * 16) * SLD + kc + aColH));
#pragma unroll
            for (int nb = 0; nb < 2; ++nb) {
                uint32_t q[4];
                ldsm4(q, s_u32(sB_ + offB + (bRow + nb * 16) * SLD + kc + bColH));
                bh[2*nb][0] = q[0]; bh[2*nb][1] = q[1];
                bh[2*nb+1][0] = q[2]; bh[2*nb+1][1] = q[3];
            }
#pragma unroll
            for (int m = 0; m < 4; ++m)
#pragma unroll
                for (int n = 0; n < 4; ++n)
                    mma_f16(acc[m][n], ah[m], bh[n]);
        }
    }
#undef LOAD_AV

    const size_t cBase = (size_t)((long long)bz * sC);
#pragma unroll
    for (int m = 0; m < 4; ++m) {
#pragma unroll
        for (int n = 0; n < 4; ++n) {
            int r0 = m0 + wr * 64 + m * 16 + g;
            int c0 = wc * 32 + n * 8 + 2 * t4;
            size_t o0 = cBase + (size_t)r0 * DMODEL + c0;
            size_t o1 = o0 + (size_t)8 * DMODEL;
            *reinterpret_cast<float2*>(Cf + o0) = make_float2(acc[m][n][0], acc[m][n][1]);
            *reinterpret_cast<float2*>(Cf + o1) = make_float2(acc[m][n][2], acc[m][n][3]);
        }
    }
}

// ---------------------------------------------------------------------------
// row softmax over 512 cols -> P fp16; one warp per row, 8 rows/block
// ---------------------------------------------------------------------------
__global__ void softmax_half_kernel(const float* __restrict__ S,
                                    __half* __restrict__ P) {
    int row = blockIdx.x * 8 + (threadIdx.x >> 5);
    int lane = threadIdx.x & 31;
    const float* r = S + (size_t)row * LQ;
    float v[16];
#pragma unroll
    for (int i = 0; i < 4; ++i) {
        float4 f = *reinterpret_cast<const float4*>(r + i * 128 + lane * 4);
        v[i * 4 + 0] = f.x; v[i * 4 + 1] = f.y; v[i * 4 + 2] = f.z; v[i * 4 + 3] = f.w;
    }
    float m = v[0];
#pragma unroll
    for (int i = 1; i < 16; ++i) m = fmaxf(m, v[i]);
#pragma unroll
    for (int o = 16; o > 0; o >>= 1) m = fmaxf(m, __shfl_xor_sync(0xffffffffu, m, o));
    float s = 0.0f;
#pragma unroll
    for (int i = 0; i < 16; ++i) { v[i] = __expf(v[i] - m); s += v[i]; }
#pragma unroll
    for (int o = 16; o > 0; o >>= 1) s += __shfl_xor_sync(0xffffffffu, s, o);
    float inv = 1.0f / s;
    __half* pr = P + (size_t)row * LQ;
#pragma unroll
    for (int i = 0; i < 4; ++i) {
        __half2 h0 = __floats2half2_rn(v[i*4+0] * inv, v[i*4+1] * inv);
        __half2 h1 = __floats2half2_rn(v[i*4+2] * inv, v[i*4+3] * inv);
        *reinterpret_cast<__half2*>(pr + i * 128 + lane * 4)     = h0;
        *reinterpret_cast<__half2*>(pr + i * 128 + lane * 4 + 2) = h1;
    }
}

// ---------------------------------------------------------------------------
extern "C" void kernel_launch(void* const* d_in, const int* in_sizes, int n_in,
                              void* d_out, int out_size)
{
    const float *x = nullptr, *y = nullptr, *W = nullptr, *bias = nullptr;
    for (int i = 0; i < n_in; ++i) {
        switch (in_sizes[i]) {
            case N_X:    x    = (const float*)d_in[i]; break;
            case N_Y:    y    = (const float*)d_in[i]; break;
            case N_W:    W    = (const float*)d_in[i]; break;
            case DMODEL: bias = (const float*)d_in[i]; break;
            default: break;
        }
    }
    float* out = (float*)d_out;

    void* base = nullptr;
    cudaGetSymbolAddress(&base, g_scratch);
    unsigned char* p = (unsigned char*)base;
    __half* x16  = (__half*)p; p += 2ull*N_X;
    __half* y16  = (__half*)p; p += 2ull*N_Y;
    __half* w_h  = (__half*)p; p += 2ull*N_W;
    __half* w_l  = (__half*)p; p += 2ull*N_W;
    __half* yT   = (__half*)p; p += 2ull*N_Y;
    __half* xp   = (__half*)p; p += 2ull*N_X;
    __half* yp_h = (__half*)p; p += 2ull*N_Y;
    __half* yp_l = (__half*)p; p += 2ull*N_Y;
    float*  S    = (float*)p;  p += 4ull*N_S;
    __half* P    = (__half*)p; p += 2ull*N_S;

    const int PSMEM  = 9 * TSZ * 2;                 // 92160 B
    const int SCSMEM = 9 * TSZ * 2;                 // 92160 B
    const int AVSMEM = (3 * TSZ + 3 * AV_BSZ) * 2;  // 92160 B
    cudaFuncSetAttribute(gemm_proj_kernel<256>,
                         cudaFuncAttributeMaxDynamicSharedMemorySize, PSMEM);
    cudaFuncSetAttribute(gemm_scores_kernel<256>,
                         cudaFuncAttributeMaxDynamicSharedMemorySize, SCSMEM);
    cudaFuncSetAttribute(gemm_av_kernel<512>,
                         cudaFuncAttributeMaxDynamicSharedMemorySize, AVSMEM);

    cvt_half_kernel<<<4096, 256>>>((const float4*)x, (uint4*)x16, N_X/8);
    split16_kernel<<<32, 256>>>((const float4*)W, (uint4*)w_h, (uint4*)w_l, N_W/8);
    y_prep_kernel<<<dim3(DMODEL/32, LQ/32, B_SZ), 256>>>(y, y16, yT);

    // merged proj: rows [0, 512) -> xp fp16; rows [512, 640) -> yp fp16 h/l
    gemm_proj_kernel<256><<<dim3(DMODEL/TN, (B_SZ*LP)/TM + (B_SZ*LQ)/TM, 1),
                            256, PSMEM>>>(
        x16, y16, w_h, w_l, xp, yp_h, yp_l, bias, DMODEL, (B_SZ*LP)/TM);

    // scores: S[b] = xp[b] @ (yp_h[b]+yp_l[b])^T  [LP, LQ]
    gemm_scores_kernel<256><<<dim3(LQ/TN, LP/TM, B_SZ), 256, SCSMEM>>>(
        xp, yp_h, yp_l, S, LQ,
        (long long)LP*DMODEL, (long long)LQ*DMODEL, (long long)LP*LQ);

    // softmax -> P fp16
    softmax_half_kernel<<<(B_SZ*LP)/8, 256>>>(S, P);

    // AV: out[b] = P[b] @ yT[b]^T  [LP, DMODEL]
    gemm_av_kernel<512><<<dim3(1, LP/TM, B_SZ), 512, AVSMEM>>>(
        P, yT, out,
        (long long)LP*LQ, (long long)DMODEL*LQ, (long long)LP*DMODEL);
}

// round 17
// speedup vs baseline: 1.0203x; 1.0203x over previous
#include <cuda_runtime.h>
#include <cuda_bf16.h>
#include <cuda_fp16.h>
#include <cstdint>
#include <cstddef>

#define B_SZ   32
#define LP     2048
#define LQ     512
#define DMODEL 256

#define N_X (B_SZ*LP*DMODEL)
#define N_Y (B_SZ*LQ*DMODEL)
#define N_W (DMODEL*DMODEL)
#define N_S ((size_t)B_SZ*LP*LQ)

__device__ __align__(1024) unsigned char g_scratch[
    2ull*N_X + 2ull*N_Y +               // x16, y16 fp16
    4ull*N_W +                           // W fp16 hi/lo
    2ull*N_Y +                           // yT fp16
    2ull*N_X +                           // xp fp16 single
    4ull*N_Y +                           // yp fp16 hi/lo
    4ull*N_S +                           // S fp32
    2ull*N_S                             // P fp16
];

// ---------------- helpers ----------------
__device__ __forceinline__ uint32_t s_u32(const void* p) {
    return (uint32_t)__cvta_generic_to_shared(p);
}
__device__ __forceinline__ void ldsm4(uint32_t* r, uint32_t a) {
    asm volatile("ldmatrix.sync.aligned.m8n8.x4.shared.b16 {%0,%1,%2,%3}, [%4];"
                 : "=r"(r[0]), "=r"(r[1]), "=r"(r[2]), "=r"(r[3]) : "r"(a));
}
__device__ __forceinline__ void mma_f16(float* c, const uint32_t* a, const uint32_t* b) {
    asm volatile("mma.sync.aligned.m16n8k16.row.col.f32.f16.f16.f32 "
                 "{%0,%1,%2,%3}, {%4,%5,%6,%7}, {%8,%9}, {%0,%1,%2,%3};"
                 : "+f"(c[0]), "+f"(c[1]), "+f"(c[2]), "+f"(c[3])
                 : "r"(a[0]), "r"(a[1]), "r"(a[2]), "r"(a[3]), "r"(b[0]), "r"(b[1]));
}
#define CPA16(s, g) asm volatile("cp.async.cg.shared.global [%0], [%1], 16;" :: "r"(s), "l"(g))

// ---------------- prep kernels ----------------
__global__ void cvt_half_kernel(const float4* __restrict__ src,
                                uint4* __restrict__ dst, int n8) {
    int i = blockIdx.x * blockDim.x + threadIdx.x;
    int st = gridDim.x * blockDim.x;
    for (; i < n8; i += st) {
        float4 a = src[2 * i], b = src[2 * i + 1];
        __half2 h0 = __floats2half2_rn(a.x, a.y);
        __half2 h1 = __floats2half2_rn(a.z, a.w);
        __half2 h2 = __floats2half2_rn(b.x, b.y);
        __half2 h3 = __floats2half2_rn(b.z, b.w);
        dst[i] = make_uint4(*reinterpret_cast<uint32_t*>(&h0),
                            *reinterpret_cast<uint32_t*>(&h1),
                            *reinterpret_cast<uint32_t*>(&h2),
                            *reinterpret_cast<uint32_t*>(&h3));
    }
}

__global__ void split16_kernel(const float4* __restrict__ src,
                               uint4* __restrict__ hi,
                               uint4* __restrict__ lo, int n8) {
    int i = blockIdx.x * blockDim.x + threadIdx.x;
    int st = gridDim.x * blockDim.x;
    for (; i < n8; i += st) {
        float4 a = src[2 * i], b = src[2 * i + 1];
        float v[8] = {a.x, a.y, a.z, a.w, b.x, b.y, b.z, b.w};
        uint32_t H[4], L[4];
#pragma unroll
        for (int j = 0; j < 4; ++j) {
            __half h0 = __float2half_rn(v[2*j]);
            __half h1 = __float2half_rn(v[2*j+1]);
            __half2 hh = __halves2half2(h0, h1);
            __half2 ll = __floats2half2_rn(v[2*j]   - __half2float(h0),
                                           v[2*j+1] - __half2float(h1));
            H[j] = *reinterpret_cast<uint32_t*>(&hh);
            L[j] = *reinterpret_cast<uint32_t*>(&ll);
        }
        hi[i] = make_uint4(H[0], H[1], H[2], H[3]);
        lo[i] = make_uint4(L[0], L[1], L[2], L[3]);
    }
}

// y [B,LQ,D] -> y16 fp16 AND yT fp16 [B,D,LQ], one read of y
__global__ void y_prep_kernel(const float* __restrict__ y,
                              __half* __restrict__ y16,
                              __half* __restrict__ t) {
    __shared__ float tile[32][33];
    int b = blockIdx.z, q0 = blockIdx.y * 32, d0 = blockIdx.x * 32;
    int tx = threadIdx.x & 31, ty = threadIdx.x >> 5;
    const float* yb = y + ((size_t)b * LQ + q0) * DMODEL + d0;
    __half* y16b = y16 + ((size_t)b * LQ + q0) * DMODEL + d0;
#pragma unroll
    for (int j = 0; j < 32; j += 8) {
        float v = yb[(size_t)(ty + j) * DMODEL + tx];
        tile[ty + j][tx] = v;
        y16b[(size_t)(ty + j) * DMODEL + tx] = __float2half_rn(v);
    }
    __syncthreads();
    __half* tb = t + ((size_t)b * DMODEL + d0) * LQ + q0;
#pragma unroll
    for (int j = 0; j < 32; j += 8)
        tb[(size_t)(ty + j) * LQ + tx] = __float2half_rn(tile[tx][ty + j]);
}

// ---------------------------------------------------------------------------
// Tiling: 128x128 CTA tile, 8 warps (2x4), warp tile 64x32, KC=32, 3-stage.
// proj: rolled loop (124 regs, 2 CTAs/SM). scores: unrolled (lean epilogue).
// ---------------------------------------------------------------------------
#define TM  128
#define TN  128
#define KC  32
#define SLD 40
#define TSZ (TM*SLD)

// ---------------------------------------------------------------------------
// Proj: 2-MMA fp16 GEMM, 3-stage, ROLLED. A = x16/y16 merged, B = W hi/lo.
// ---------------------------------------------------------------------------
template<int KT>
__global__ void __launch_bounds__(256) gemm_proj_kernel(
    const __half* __restrict__ A1, const __half* __restrict__ A2,
    const __half* __restrict__ Wh, const __half* __restrict__ Wl,
    __half* __restrict__ Xp,
    __half* __restrict__ YpH, __half* __restrict__ YpL,
    const float* __restrict__ bias, int N, int Msplit)
{
    extern __shared__ __align__(16) __half dynp[];
    __half* sA_ = dynp;                 // 3 stages x TSZ
    __half* sBh = dynp + 3 * TSZ;
    __half* sBl = dynp + 6 * TSZ;

    const int tid = threadIdx.x;
    int m0 = blockIdx.y * TM;
    const int n0 = blockIdx.x * TN;

    const __half* Au = A1;
    const bool isY = (int)blockIdx.y >= Msplit;
    if (isY) { Au = A2; m0 = ((int)blockIdx.y - Msplit) * TM; }

    const int r0l = tid >> 2, hl = (tid & 3) * 8;
    const __half* pA  = Au + (size_t)m0 * KT;
    const __half* pBh = Wh + (size_t)n0 * KT;
    const __half* pBl = Wl + (size_t)n0 * KT;

#define LOAD_CHUNK(c, buf) do {                                               \
        const int _ko = (c) * KC;                                             \
        _Pragma("unroll")                                                     \
        for (int _i = 0; _i < 2; ++_i) {                                      \
            int _r = _i * 64 + r0l;                                           \
            int _so = (buf) * TSZ + _r * SLD + hl;                            \
            size_t _go = (size_t)_r * KT + _ko + hl;                          \
            CPA16(s_u32(sA_ + _so), pA  + _go);                               \
            CPA16(s_u32(sBh + _so), pBh + _go);                               \
            CPA16(s_u32(sBl + _so), pBl + _go);                               \
        }                                                                     \
        asm volatile("cp.async.commit_group;" ::: "memory");                  \
    } while (0)

    const int lane = tid & 31, warp = tid >> 5;
    const int wr = warp >> 2, wc = warp & 3;
    const int g = lane >> 2, t4 = lane & 3;
    const int aRow = wr * 64 + (lane & 15);
    const int aColH = (lane >> 4) << 3;
    const int bRow = wc * 32 + ((lane >> 4) << 3) + (lane & 7);
    const int bColH = ((lane >> 3) & 1) << 3;

    float acc[4][4][4];
#pragma unroll
    for (int m = 0; m < 4; ++m)
#pragma unroll
        for (int n = 0; n < 4; ++n)
#pragma unroll
            for (int k = 0; k < 4; ++k) acc[m][n][k] = 0.0f;

    constexpr int NC = KT / KC;     // 8
    LOAD_CHUNK(0, 0);
    LOAD_CHUNK(1, 1);
#pragma unroll 1
    for (int c = 0; c < NC; ++c) {
        if (c < NC - 1) asm volatile("cp.async.wait_group 1;" ::: "memory");
        else            asm volatile("cp.async.wait_group 0;" ::: "memory");
        __syncthreads();
        if (c + 2 < NC) LOAD_CHUNK(c + 2, (c + 2) % 3);
        const int off = (c % 3) * TSZ;

#pragma unroll
        for (int ks = 0; ks < 2; ++ks) {
            const int kc = ks * 16;
            uint32_t ah[4][4], bh[4][2], bl[4][2];
#pragma unroll
            for (int m = 0; m < 4; ++m)
                ldsm4(ah[m], s_u32(sA_ + off + (aRow + m * 16) * SLD + kc + aColH));
#pragma unroll
            for (int nb = 0; nb < 2; ++nb) {
                int bo = off + (bRow + nb * 16) * SLD + kc + bColH;
                uint32_t qh[4], ql[4];
                ldsm4(qh, s_u32(sBh + bo));
                ldsm4(ql, s_u32(sBl + bo));
                bh[2*nb][0] = qh[0]; bh[2*nb][1] = qh[1];
                bh[2*nb+1][0] = qh[2]; bh[2*nb+1][1] = qh[3];
                bl[2*nb][0] = ql[0]; bl[2*nb][1] = ql[1];
                bl[2*nb+1][0] = ql[2]; bl[2*nb+1][1] = ql[3];
            }
#pragma unroll
            for (int m = 0; m < 4; ++m)
#pragma unroll
                for (int n = 0; n < 4; ++n) {
                    mma_f16(acc[m][n], ah[m], bh[n]);
                    mma_f16(acc[m][n], ah[m], bl[n]);
                }
        }
    }
#undef LOAD_CHUNK

#pragma unroll
    for (int m = 0; m < 4; ++m) {
#pragma unroll
        for (int n = 0; n < 4; ++n) {
            int r0 = m0 + wr * 64 + m * 16 + g;
            int c0 = n0 + wc * 32 + n * 8 + 2 * t4;
            size_t o0 = (size_t)r0 * N + c0;
            size_t o1 = o0 + (size_t)8 * N;
            float b0 = __ldg(bias + c0), b1 = __ldg(bias + c0 + 1);
            float a0 = fmaxf(acc[m][n][0] + b0, 0.0f);
            float a1 = fmaxf(acc[m][n][1] + b1, 0.0f);
            float a2 = fmaxf(acc[m][n][2] + b0, 0.0f);
            float a3 = fmaxf(acc[m][n][3] + b1, 0.0f);
            if (!isY) {
                *reinterpret_cast<__half2*>(Xp + o0) = __floats2half2_rn(a0, a1);
                *reinterpret_cast<__half2*>(Xp + o1) = __floats2half2_rn(a2, a3);
            } else {
                __half h0 = __float2half_rn(a0), h1 = __float2half_rn(a1);
                __half h2 = __float2half_rn(a2), h3 = __float2half_rn(a3);
                *reinterpret_cast<__half2*>(YpH + o0) = __halves2half2(h0, h1);
                *reinterpret_cast<__half2*>(YpH + o1) = __halves2half2(h2, h3);
                *reinterpret_cast<__half2*>(YpL + o0) = __floats2half2_rn(
                    a0 - __half2float(h0), a1 - __half2float(h1));
                *reinterpret_cast<__half2*>(YpL + o1) = __floats2half2_rn(
                    a2 - __half2float(h2), a3 - __half2float(h3));
            }
        }
    }
}

// ---------------------------------------------------------------------------
// Scores: S[b] = Xp[b] @ (YpH[b]+YpL[b])^T — fp16, 2 MMAs, 3-stage, UNROLLED.
// ---------------------------------------------------------------------------
template<int KT>
__global__ void __launch_bounds__(256) gemm_scores_kernel(
    const __half* __restrict__ A,
    const __half* __restrict__ BH, const __half* __restrict__ BL,
    float* __restrict__ Cf, int N,
    long long sA, long long sB, long long sC)
{
    extern __shared__ __align__(16) __half dynh[];
    __half* sA_ = dynh;
    __half* sBh = dynh + 3 * TSZ;
    __half* sBl = dynh + 6 * TSZ;

    const int tid = threadIdx.x;
    const int bz = blockIdx.z;
    const int m0 = blockIdx.y * TM, n0 = blockIdx.x * TN;

    const int r0l = tid >> 2, hl = (tid & 3) * 8;
    const __half* pA  = A  + bz * sA + (size_t)m0 * KT;
    const __half* pBh = BH + bz * sB + (size_t)n0 * KT;
    const __half* pBl = BL + bz * sB + (size_t)n0 * KT;

#define LOAD_SC(c, buf) do {                                                  \
        const int _ko = (c) * KC;                                             \
        _Pragma("unroll")                                                     \
        for (int _i = 0; _i < 2; ++_i) {                                      \
            int _r = _i * 64 + r0l;                                           \
            int _so = (buf) * TSZ + _r * SLD + hl;                            \
            size_t _go = (size_t)_r * KT + _ko + hl;                          \
            CPA16(s_u32(sA_ + _so), pA  + _go);                               \
            CPA16(s_u32(sBh + _so), pBh + _go);                               \
            CPA16(s_u32(sBl + _so), pBl + _go);                               \
        }                                                                     \
        asm volatile("cp.async.commit_group;" ::: "memory");                  \
    } while (0)

    const int lane = tid & 31, warp = tid >> 5;
    const int wr = warp >> 2, wc = warp & 3;
    const int g = lane >> 2, t4 = lane & 3;
    const int aRow = wr * 64 + (lane & 15);
    const int aColH = (lane >> 4) << 3;
    const int bRow = wc * 32 + ((lane >> 4) << 3) + (lane & 7);
    const int bColH = ((lane >> 3) & 1) << 3;

    float acc[4][4][4];
#pragma unroll
    for (int m = 0; m < 4; ++m)
#pragma unroll
        for (int n = 0; n < 4; ++n)
#pragma unroll
            for (int k = 0; k < 4; ++k) acc[m][n][k] = 0.0f;

    constexpr int NC = KT / KC;     // 8
    LOAD_SC(0, 0);
    LOAD_SC(1, 1);
#pragma unroll
    for (int c = 0; c < NC; ++c) {
        if (c < NC - 1) asm volatile("cp.async.wait_group 1;" ::: "memory");
        else            asm volatile("cp.async.wait_group 0;" ::: "memory");
        __syncthreads();
        if (c + 2 < NC) LOAD_SC(c + 2, (c + 2) % 3);
        const int off = (c % 3) * TSZ;

#pragma unroll
        for (int ks = 0; ks < 2; ++ks) {
            const int kc = ks * 16;
            uint32_t ah[4][4], bh[4][2], bl[4][2];
#pragma unroll
            for (int m = 0; m < 4; ++m)
                ldsm4(ah[m], s_u32(sA_ + off + (aRow + m * 16) * SLD + kc + aColH));
#pragma unroll
            for (int nb = 0; nb < 2; ++nb) {
                int bo = off + (bRow + nb * 16) * SLD + kc + bColH;
                uint32_t qh[4], ql[4];
                ldsm4(qh, s_u32(sBh + bo));
                ldsm4(ql, s_u32(sBl + bo));
                bh[2*nb][0] = qh[0]; bh[2*nb][1] = qh[1];
                bh[2*nb+1][0] = qh[2]; bh[2*nb+1][1] = qh[3];
                bl[2*nb][0] = ql[0]; bl[2*nb][1] = ql[1];
                bl[2*nb+1][0] = ql[2]; bl[2*nb+1][1] = ql[3];
            }
#pragma unroll
            for (int m = 0; m < 4; ++m)
#pragma unroll
                for (int n = 0; n < 4; ++n) {
                    mma_f16(acc[m][n], ah[m], bh[n]);
                    mma_f16(acc[m][n], ah[m], bl[n]);
                }
        }
    }
#undef LOAD_SC

    const size_t cBase = (size_t)((long long)bz * sC);
#pragma unroll
    for (int m = 0; m < 4; ++m) {
#pragma unroll
        for (int n = 0; n < 4; ++n) {
            int r0 = m0 + wr * 64 + m * 16 + g;
            int c0 = n0 + wc * 32 + n * 8 + 2 * t4;
            size_t o0 = cBase + (size_t)r0 * N + c0;
            size_t o1 = o0 + (size_t)8 * N;
            *reinterpret_cast<float2*>(Cf + o0) = make_float2(acc[m][n][0], acc[m][n][1]);
            *reinterpret_cast<float2*>(Cf + o1) = make_float2(acc[m][n][2], acc[m][n][3]);
        }
    }
}

// ---------------------------------------------------------------------------
// AV: fp16 GEMM, CTA tile 128x256, 512 threads, 3-stage (R15-proven).
// ---------------------------------------------------------------------------
#define AV_BSZ (256*SLD)

template<int KT>
__global__ void __launch_bounds__(512) gemm_av_kernel(
    const __half* __restrict__ A, const __half* __restrict__ B,
    float* __restrict__ Cf,
    long long sA, long long sB, long long sC)
{
    extern __shared__ __align__(16) __half dynav[];
    __half* sA_ = dynav;                 // 3 x TSZ
    __half* sB_ = dynav + 3 * TSZ;       // 3 x AV_BSZ

    const int tid = threadIdx.x;
    const int bz = blockIdx.z;
    const int m0 = blockIdx.y * TM;

    const __half* pA = A + bz * sA + (size_t)m0 * KT;
    const __half* pB = B + bz * sB;

    const int rA = tid >> 2, hA = (tid & 3) * 8;

#define LOAD_AV(c, buf) do {                                                  \
        const int _ko = (c) * KC;                                             \
        CPA16(s_u32(sA_ + (buf) * TSZ + rA * SLD + hA),                       \
              pA + (size_t)rA * KT + _ko + hA);                               \
        _Pragma("unroll")                                                     \
        for (int _i = 0; _i < 2; ++_i) {                                      \
            int _idx = _i * 512 + tid;                                        \
            int _r = _idx >> 2, _h = (_idx & 3) * 8;                          \
            CPA16(s_u32(sB_ + (buf) * AV_BSZ + _r * SLD + _h),                \
                  pB + (size_t)_r * KT + _ko + _h);                           \
        }                                                                     \
        asm volatile("cp.async.commit_group;" ::: "memory");                  \
    } while (0)

    const int lane = tid & 31, warp = tid >> 5;
    const int wr = warp >> 3, wc = warp & 7;
    const int g = lane >> 2, t4 = lane & 3;
    const int aRow = wr * 64 + (lane & 15);
    const int aColH = (lane >> 4) << 3;
    const int bRow = wc * 32 + ((lane >> 4) << 3) + (lane & 7);
    const int bColH = ((lane >> 3) & 1) << 3;

    float acc[4][4][4];
#pragma unroll
    for (int m = 0; m < 4; ++m)
#pragma unroll
        for (int n = 0; n < 4; ++n)
#pragma unroll
            for (int k = 0; k < 4; ++k) acc[m][n][k] = 0.0f;

    constexpr int NC = KT / KC;     // 16
    LOAD_AV(0, 0);
    LOAD_AV(1, 1);
#pragma unroll 1
    for (int c = 0; c < NC; ++c) {
        if (c < NC - 1) asm volatile("cp.async.wait_group 1;" ::: "memory");
        else            asm volatile("cp.async.wait_group 0;" ::: "memory");
        __syncthreads();
        if (c + 2 < NC) LOAD_AV(c + 2, (c + 2) % 3);
        const int offA = (c % 3) * TSZ, offB = (c % 3) * AV_BSZ;

#pragma unroll
        for (int ks = 0; ks < 2; ++ks) {
            const int kc = ks * 16;
            uint32_t ah[4][4], bh[4][2];
#pragma unroll
            for (int m = 0; m < 4; ++m)
                ldsm4(ah[m], s_u32(sA_ + offA + (aRow + m * 16) * SLD + kc + aColH));
#pragma unroll
            for (int nb = 0; nb < 2; ++nb) {
                uint32_t q[4];
                ldsm4(q, s_u32(sB_ + offB + (bRow + nb * 16) * SLD + kc + bColH));
                bh[2*nb][0] = q[0]; bh[2*nb][1] = q[1];
                bh[2*nb+1][0] = q[2]; bh[2*nb+1][1] = q[3];
            }
#pragma unroll
            for (int m = 0; m < 4; ++m)
#pragma unroll
                for (int n = 0; n < 4; ++n)
                    mma_f16(acc[m][n], ah[m], bh[n]);
        }
    }
#undef LOAD_AV

    const size_t cBase = (size_t)((long long)bz * sC);
#pragma unroll
    for (int m = 0; m < 4; ++m) {
#pragma unroll
        for (int n = 0; n < 4; ++n) {
            int r0 = m0 + wr * 64 + m * 16 + g;
            int c0 = wc * 32 + n * 8 + 2 * t4;
            size_t o0 = cBase + (size_t)r0 * DMODEL + c0;
            size_t o1 = o0 + (size_t)8 * DMODEL;
            *reinterpret_cast<float2*>(Cf + o0) = make_float2(acc[m][n][0], acc[m][n][1]);
            *reinterpret_cast<float2*>(Cf + o1) = make_float2(acc[m][n][2], acc[m][n][3]);
        }
    }
}

// ---------------------------------------------------------------------------
// row softmax over 512 cols -> P fp16; one warp per row, 8 rows/block
// ---------------------------------------------------------------------------
__global__ void softmax_half_kernel(const float* __restrict__ S,
                                    __half* __restrict__ P) {
    int row = blockIdx.x * 8 + (threadIdx.x >> 5);
    int lane = threadIdx.x & 31;
    const float* r = S + (size_t)row * LQ;
    float v[16];
#pragma unroll
    for (int i = 0; i < 4; ++i) {
        float4 f = *reinterpret_cast<const float4*>(r + i * 128 + lane * 4);
        v[i * 4 + 0] = f.x; v[i * 4 + 1] = f.y; v[i * 4 + 2] = f.z; v[i * 4 + 3] = f.w;
    }
    float m = v[0];
#pragma unroll
    for (int i = 1; i < 16; ++i) m = fmaxf(m, v[i]);
#pragma unroll
    for (int o = 16; o > 0; o >>= 1) m = fmaxf(m, __shfl_xor_sync(0xffffffffu, m, o));
    float s = 0.0f;
#pragma unroll
    for (int i = 0; i < 16; ++i) { v[i] = __expf(v[i] - m); s += v[i]; }
#pragma unroll
    for (int o = 16; o > 0; o >>= 1) s += __shfl_xor_sync(0xffffffffu, s, o);
    float inv = 1.0f / s;
    __half* pr = P + (size_t)row * LQ;
#pragma unroll
    for (int i = 0; i < 4; ++i) {
        __half2 h0 = __floats2half2_rn(v[i*4+0] * inv, v[i*4+1] * inv);
        __half2 h1 = __floats2half2_rn(v[i*4+2] * inv, v[i*4+3] * inv);
        *reinterpret_cast<__half2*>(pr + i * 128 + lane * 4)     = h0;
        *reinterpret_cast<__half2*>(pr + i * 128 + lane * 4 + 2) = h1;
    }
}

// ---------------------------------------------------------------------------
extern "C" void kernel_launch(void* const* d_in, const int* in_sizes, int n_in,
                              void* d_out, int out_size)
{
    const float *x = nullptr, *y = nullptr, *W = nullptr, *bias = nullptr;
    for (int i = 0; i < n_in; ++i) {
        switch (in_sizes[i]) {
            case N_X:    x    = (const float*)d_in[i]; break;
            case N_Y:    y    = (const float*)d_in[i]; break;
            case N_W:    W    = (const float*)d_in[i]; break;
            case DMODEL: bias = (const float*)d_in[i]; break;
            default: break;
        }
    }
    float* out = (float*)d_out;

    void* base = nullptr;
    cudaGetSymbolAddress(&base, g_scratch);
    unsigned char* p = (unsigned char*)base;
    __half* x16  = (__half*)p; p += 2ull*N_X;
    __half* y16  = (__half*)p; p += 2ull*N_Y;
    __half* w_h  = (__half*)p; p += 2ull*N_W;
    __half* w_l  = (__half*)p; p += 2ull*N_W;
    __half* yT   = (__half*)p; p += 2ull*N_Y;
    __half* xp   = (__half*)p; p += 2ull*N_X;
    __half* yp_h = (__half*)p; p += 2ull*N_Y;
    __half* yp_l = (__half*)p; p += 2ull*N_Y;
    float*  S    = (float*)p;  p += 4ull*N_S;
    __half* P    = (__half*)p; p += 2ull*N_S;

    const int PSMEM  = 9 * TSZ * 2;                 // 92160 B
    const int SCSMEM = 9 * TSZ * 2;                 // 92160 B
    const int AVSMEM = (3 * TSZ + 3 * AV_BSZ) * 2;  // 92160 B
    cudaFuncSetAttribute(gemm_proj_kernel<256>,
                         cudaFuncAttributeMaxDynamicSharedMemorySize, PSMEM);
    cudaFuncSetAttribute(gemm_scores_kernel<256>,
                         cudaFuncAttributeMaxDynamicSharedMemorySize, SCSMEM);
    cudaFuncSetAttribute(gemm_av_kernel<512>,
                         cudaFuncAttributeMaxDynamicSharedMemorySize, AVSMEM);

    cvt_half_kernel<<<4096, 256>>>((const float4*)x, (uint4*)x16, N_X/8);
    split16_kernel<<<32, 256>>>((const float4*)W, (uint4*)w_h, (uint4*)w_l, N_W/8);
    y_prep_kernel<<<dim3(DMODEL/32, LQ/32, B_SZ), 256>>>(y, y16, yT);

    // merged proj: rows [0, 512) -> xp fp16; rows [512, 640) -> yp fp16 h/l
    gemm_proj_kernel<256><<<dim3(DMODEL/TN, (B_SZ*LP)/TM + (B_SZ*LQ)/TM, 1),
                            256, PSMEM>>>(
        x16, y16, w_h, w_l, xp, yp_h, yp_l, bias, DMODEL, (B_SZ*LP)/TM);

    // scores: S[b] = xp[b] @ (yp_h[b]+yp_l[b])^T  [LP, LQ]
    gemm_scores_kernel<256><<<dim3(LQ/TN, LP/TM, B_SZ), 256, SCSMEM>>>(
        xp, yp_h, yp_l, S, LQ,
        (long long)LP*DMODEL, (long long)LQ*DMODEL, (long long)LP*LQ);

    // softmax -> P fp16
    softmax_half_kernel<<<(B_SZ*LP)/8, 256>>>(S, P);

    // AV: out[b] = P[b] @ yT[b]^T  [LP, DMODEL]
    gemm_av_kernel<512><<<dim3(1, LP/TM, B_SZ), 512, AVSMEM>>>(
        P, yT, out,
        (long long)LP*LQ, (long long)DMODEL*LQ, (long long)LP*DMODEL);
}